// round 3
// baseline (speedup 1.0000x reference)
#include <cuda_runtime.h>
#include <cuda_bf16.h>
#include <math.h>

// Problem dims (fixed)
#define B_  64
#define T_  512
#define E_  256
#define H_  256
#define O_  256
#define M_  (T_ * B_)          // 32768 rows (t-major, b-minor)

// Scan W_hh split: KREG rows in registers (one column per thread), KSH rows in shared
#define KREG 160
#define KSH  (H_ - KREG)       // 96
#define SMEM_SCAN ((2 * H_ + KSH * H_) * sizeof(float))   // h double buffer + Wsh

// ---------------------------------------------------------------------------
// Static device scratch (no allocation allowed)
// ---------------------------------------------------------------------------
__device__ float g_xf[(size_t)T_ * B_ * H_];   // xf[t][b][j]   (32 MB)
__device__ float g_xb[(size_t)T_ * B_ * H_];   // xb[s][b][j], s = scan index (32 MB)
__device__ float g_h [(size_t)M_ * (2 * H_)];  // hcat[t*64+b][0:256]=hf, [256:512]=hb (64 MB)

// ---------------------------------------------------------------------------
// Kernel 1: fused input projections (both directions, one pass over X)
//   xf[t,b,j] = sum_e X[b,t,e]*Wf[e,j] + bf[j]
//   xb[s,b,j] = sum_e X[b,T-1-s,e]*Wb[e,j] + bb[j]   (written at s = T-1-t)
// 128x64 tile, BK=16, 256 threads, 8x4 microtile, two accumulator sets.
// ---------------------------------------------------------------------------
__global__ __launch_bounds__(256) void proj_kernel(
    const float* __restrict__ X,
    const float* __restrict__ Wf, const float* __restrict__ bfv,
    const float* __restrict__ Wb, const float* __restrict__ bbv)
{
    __shared__ float As [16][132];  // [k][m], padded
    __shared__ float Bfs[16][68];   // [k][j], padded
    __shared__ float Bbs[16][68];

    const int tid = threadIdx.x;
    const int m0 = blockIdx.y * 128;
    const int j0 = blockIdx.x * 64;

    const int rbase = (tid >> 4) * 8;     // 0..120
    const int cbase = (tid & 15) * 4;     // 0..60

    // A-tile load mapping: each thread loads 8 floats of one row
    const int lr = tid >> 1;              // 0..127
    const int lc = (tid & 1) * 8;         // 0 or 8
    const int gm = m0 + lr;
    // gather: row m -> X[b][t][:] with t = m>>6, b = m&63
    const float* arow = X + ((size_t)(gm & 63) * T_ + (gm >> 6)) * E_;

    // B-tile load mapping
    const int bk = tid >> 4;              // 0..15
    const int bj = (tid & 15) * 4;        // 0..60

    float acc_f[8][4], acc_b[8][4];
#pragma unroll
    for (int i = 0; i < 8; i++)
#pragma unroll
        for (int j = 0; j < 4; j++) { acc_f[i][j] = 0.f; acc_b[i][j] = 0.f; }

    for (int e0 = 0; e0 < E_; e0 += 16) {
        float4 a0 = *(const float4*)(arow + e0 + lc);
        float4 a1 = *(const float4*)(arow + e0 + lc + 4);
        float4 f4 = *(const float4*)(Wf + (size_t)(e0 + bk) * H_ + j0 + bj);
        float4 b4 = *(const float4*)(Wb + (size_t)(e0 + bk) * H_ + j0 + bj);
        __syncthreads();
        As[lc + 0][lr] = a0.x; As[lc + 1][lr] = a0.y;
        As[lc + 2][lr] = a0.z; As[lc + 3][lr] = a0.w;
        As[lc + 4][lr] = a1.x; As[lc + 5][lr] = a1.y;
        As[lc + 6][lr] = a1.z; As[lc + 7][lr] = a1.w;
        *(float4*)&Bfs[bk][bj] = f4;
        *(float4*)&Bbs[bk][bj] = b4;
        __syncthreads();
#pragma unroll
        for (int kk = 0; kk < 16; kk++) {
            float a[8], fb[4], bb_[4];
#pragma unroll
            for (int i = 0; i < 8; i++) a[i] = As[kk][rbase + i];
#pragma unroll
            for (int j = 0; j < 4; j++) { fb[j] = Bfs[kk][cbase + j]; bb_[j] = Bbs[kk][cbase + j]; }
#pragma unroll
            for (int i = 0; i < 8; i++)
#pragma unroll
                for (int j = 0; j < 4; j++) {
                    acc_f[i][j] += a[i] * fb[j];
                    acc_b[i][j] += a[i] * bb_[j];
                }
        }
    }

    // epilogue
#pragma unroll
    for (int i = 0; i < 8; i++) {
        const int m = m0 + rbase + i;
        const int t = m >> 6, b = m & 63;
        const int m2 = (T_ - 1 - t) * B_ + b;      // scan index slot for xb
        float4 vf, vb;
        vf.x = acc_f[i][0] + bfv[j0 + cbase + 0];
        vf.y = acc_f[i][1] + bfv[j0 + cbase + 1];
        vf.z = acc_f[i][2] + bfv[j0 + cbase + 2];
        vf.w = acc_f[i][3] + bfv[j0 + cbase + 3];
        vb.x = acc_b[i][0] + bbv[j0 + cbase + 0];
        vb.y = acc_b[i][1] + bbv[j0 + cbase + 1];
        vb.z = acc_b[i][2] + bbv[j0 + cbase + 2];
        vb.w = acc_b[i][3] + bbv[j0 + cbase + 3];
        *(float4*)&g_xf[(size_t)m  * H_ + j0 + cbase] = vf;
        *(float4*)&g_xb[(size_t)m2 * H_ + j0 + cbase] = vb;
    }
}

// ---------------------------------------------------------------------------
// Kernel 2: persistent per-(batch,direction) recurrent scan.
// 128 blocks, 256 threads. Thread t owns output column j=t.
// W_hh column split: rows [0,KREG) in registers, rows [KREG,256) in shared.
// One __syncthreads per step (double-buffered h).
// ---------------------------------------------------------------------------
extern __shared__ float smem_scan[];

__global__ __launch_bounds__(256) void scan_kernel(
    const float* __restrict__ Whh_f,
    const float* __restrict__ Whh_b,
    float* __restrict__ out)
{
    float* h_sh = smem_scan;            // [2][256]
    float* Wsh  = smem_scan + 2 * H_;   // [KSH][256]

    const int t   = threadIdx.x;
    const int dir = blockIdx.x >> 6;    // 0 = fwd, 1 = bwd
    const int b   = blockIdx.x & 63;

    const float* W    = dir ? Whh_b : Whh_f;
    const float* xarr = dir ? g_xb  : g_xf;

    // load my W column: register part
    float wreg[KREG];
#pragma unroll
    for (int k = 0; k < KREG; k++) wreg[k] = W[(size_t)k * H_ + t];
    // shared part (cooperative, coalesced in j)
    for (int r = 0; r < KSH; r++) Wsh[r * H_ + t] = W[(size_t)(KREG + r) * H_ + t];
    h_sh[t] = 0.f;
    __syncthreads();

    const float* xp = xarr + (size_t)b * H_ + t;  // step stride = B_*H_
    float x_next = xp[0];
    float hlast = 0.f;
    int p = 0;

    for (int s = 0; s < T_; ++s) {
        float a0 = x_next, a1 = 0.f, a2 = 0.f, a3 = 0.f;  // 4 partial accumulators
        if (s + 1 < T_) x_next = xp[(size_t)(s + 1) * (B_ * H_)];

        const float*  hc  = h_sh + p * H_;
        const float4* hc4 = (const float4*)hc;

        // register-resident W rows
#pragma unroll
        for (int k4 = 0; k4 < KREG / 4; k4++) {
            float4 hv = hc4[k4];
            a0 += hv.x * wreg[4 * k4 + 0];
            a1 += hv.y * wreg[4 * k4 + 1];
            a2 += hv.z * wreg[4 * k4 + 2];
            a3 += hv.w * wreg[4 * k4 + 3];
        }
        // shared-resident W rows
#pragma unroll
        for (int r4 = 0; r4 < KSH / 4; r4++) {
            float4 hv = hc4[KREG / 4 + r4];
            a0 += hv.x * Wsh[(4 * r4 + 0) * H_ + t];
            a1 += hv.y * Wsh[(4 * r4 + 1) * H_ + t];
            a2 += hv.z * Wsh[(4 * r4 + 2) * H_ + t];
            a3 += hv.w * Wsh[(4 * r4 + 3) * H_ + t];
        }

        float hn = tanhf((a0 + a1) + (a2 + a3));
        h_sh[(p ^ 1) * H_ + t] = hn;

        // store into concatenated history at the ORIGINAL time index
        const int t_orig = dir ? (T_ - 1 - s) : s;
        g_h[((size_t)(t_orig * B_ + b)) * (2 * H_) + dir * H_ + t] = hn;

        hlast = hn;
        p ^= 1;
        __syncthreads();
    }

    // final carry states: hf_last / hb_last, layout [b][j]
    out[(size_t)B_ * T_ * O_ + (size_t)dir * (B_ * H_) + (size_t)b * H_ + t] = hlast;
}

// ---------------------------------------------------------------------------
// Kernel 3: output GEMM  Y[b,t,o] = sum_{k<512} hcat[t*64+b][k] * W_hy[k][o] + b_y[o]
// 128x64 tile, BK=16, K=512. A rows are contiguous (stride 512).
// ---------------------------------------------------------------------------
__global__ __launch_bounds__(256) void out_kernel(
    const float* __restrict__ Why, const float* __restrict__ byv,
    float* __restrict__ out)
{
    __shared__ float As[16][132];
    __shared__ float Bs[16][68];

    const int tid = threadIdx.x;
    const int m0 = blockIdx.y * 128;
    const int j0 = blockIdx.x * 64;

    const int rbase = (tid >> 4) * 8;
    const int cbase = (tid & 15) * 4;

    const int lr = tid >> 1;
    const int lc = (tid & 1) * 8;
    const float* arow = g_h + (size_t)(m0 + lr) * (2 * H_);

    const int bk = tid >> 4;
    const int bj = (tid & 15) * 4;

    float acc[8][4];
#pragma unroll
    for (int i = 0; i < 8; i++)
#pragma unroll
        for (int j = 0; j < 4; j++) acc[i][j] = 0.f;

    for (int e0 = 0; e0 < 2 * H_; e0 += 16) {
        float4 a0 = *(const float4*)(arow + e0 + lc);
        float4 a1 = *(const float4*)(arow + e0 + lc + 4);
        float4 w4 = *(const float4*)(Why + (size_t)(e0 + bk) * O_ + j0 + bj);
        __syncthreads();
        As[lc + 0][lr] = a0.x; As[lc + 1][lr] = a0.y;
        As[lc + 2][lr] = a0.z; As[lc + 3][lr] = a0.w;
        As[lc + 4][lr] = a1.x; As[lc + 5][lr] = a1.y;
        As[lc + 6][lr] = a1.z; As[lc + 7][lr] = a1.w;
        *(float4*)&Bs[bk][bj] = w4;
        __syncthreads();
#pragma unroll
        for (int kk = 0; kk < 16; kk++) {
            float a[8], bw[4];
#pragma unroll
            for (int i = 0; i < 8; i++) a[i] = As[kk][rbase + i];
#pragma unroll
            for (int j = 0; j < 4; j++) bw[j] = Bs[kk][cbase + j];
#pragma unroll
            for (int i = 0; i < 8; i++)
#pragma unroll
                for (int j = 0; j < 4; j++) acc[i][j] += a[i] * bw[j];
        }
    }

#pragma unroll
    for (int i = 0; i < 8; i++) {
        const int m = m0 + rbase + i;
        const int t = m >> 6, b = m & 63;
        float4 v;
        v.x = acc[i][0] + byv[j0 + cbase + 0];
        v.y = acc[i][1] + byv[j0 + cbase + 1];
        v.z = acc[i][2] + byv[j0 + cbase + 2];
        v.w = acc[i][3] + byv[j0 + cbase + 3];
        *(float4*)&out[((size_t)b * T_ + t) * O_ + j0 + cbase] = v;
    }
}

// ---------------------------------------------------------------------------
// launch
// ---------------------------------------------------------------------------
extern "C" void kernel_launch(void* const* d_in, const int* in_sizes, int n_in,
                              void* d_out, int out_size)
{
    const float* X    = (const float*)d_in[0];
    const float* Wxhf = (const float*)d_in[1];
    const float* Whhf = (const float*)d_in[2];
    const float* bf   = (const float*)d_in[3];
    const float* Wxhb = (const float*)d_in[4];
    const float* Whhb = (const float*)d_in[5];
    const float* bb   = (const float*)d_in[6];
    const float* Why  = (const float*)d_in[7];
    const float* by   = (const float*)d_in[8];
    float* out = (float*)d_out;

    cudaFuncSetAttribute(scan_kernel,
                         cudaFuncAttributeMaxDynamicSharedMemorySize,
                         (int)SMEM_SCAN);

    proj_kernel<<<dim3(4, 256), 256>>>(X, Wxhf, bf, Wxhb, bb);
    scan_kernel<<<128, 256, SMEM_SCAN>>>(Whhf, Whhb, out);
    out_kernel<<<dim3(4, 256), 256>>>(Why, by, out);
}

// round 4
// speedup vs baseline: 1.0493x; 1.0493x over previous
#include <cuda_runtime.h>
#include <cuda_bf16.h>
#include <math.h>

// Problem dims (fixed)
#define B_  64
#define T_  512
#define E_  256
#define H_  256
#define O_  256
#define M_  (T_ * B_)          // 32768 rows (t-major, b-minor)

// Scan W_hh split: 160 rows (80 f32x2 pairs) in registers, 96 rows in shared (float4 groups)
#define KREGP 80               // register pairs   (k = 0..159)
#define KSH4  24               // shared float4 groups (k = 160..255)
#define SMEM_SCAN ((2 * H_) * sizeof(float) + (KSH4 * H_) * sizeof(float4))

// ---------------------------------------------------------------------------
// f32x2 packed-FMA helpers (sm_100a)
// ---------------------------------------------------------------------------
__device__ __forceinline__ unsigned long long pk2(float lo, float hi) {
    unsigned long long r;
    asm("mov.b64 %0, {%1, %2};" : "=l"(r) : "f"(lo), "f"(hi));
    return r;
}
__device__ __forceinline__ void upk2(unsigned long long v, float& lo, float& hi) {
    asm("mov.b64 {%0, %1}, %2;" : "=f"(lo), "=f"(hi) : "l"(v));
}
#define FMA2(d, a, b, c) \
    asm("fma.rn.f32x2 %0, %1, %2, %3;" : "=l"(d) : "l"(a), "l"(b), "l"(c))

__device__ __forceinline__ float fast_tanh(float v) {
    float x = fminf(fmaxf(v, -15.f), 15.f);
    float e = __expf(2.f * x);
    return __fdividef(e - 1.f, e + 1.f);
}

// ---------------------------------------------------------------------------
// Static device scratch (no allocation allowed)
// ---------------------------------------------------------------------------
__device__ float g_xf[(size_t)T_ * B_ * H_];   // xf[t][b][j]   (32 MB)
__device__ float g_xb[(size_t)T_ * B_ * H_];   // xb[s][b][j], s = scan index (32 MB)
__device__ float g_h [(size_t)M_ * (2 * H_)];  // hcat[t*64+b][0:256]=hf, [256:512]=hb (64 MB)

// ---------------------------------------------------------------------------
// Kernel 1: fused input projections (both directions, one pass over X)
// 128x64 tile, BK=16, 256 threads, 8x4 microtile, FFMA2 (rows paired).
// ---------------------------------------------------------------------------
__global__ __launch_bounds__(256) void proj_kernel(
    const float* __restrict__ X,
    const float* __restrict__ Wf, const float* __restrict__ bfv,
    const float* __restrict__ Wb, const float* __restrict__ bbv)
{
    __shared__ float As [16][132];  // [k][m], padded
    __shared__ float Bfs[16][68];   // [k][j], padded
    __shared__ float Bbs[16][68];

    const int tid = threadIdx.x;
    const int m0 = blockIdx.y * 128;
    const int j0 = blockIdx.x * 64;

    const int rbase = (tid >> 4) * 8;     // 0..120
    const int cbase = (tid & 15) * 4;     // 0..60

    const int lr = tid >> 1;              // 0..127
    const int lc = (tid & 1) * 8;         // 0 or 8
    const int gm = m0 + lr;
    const float* arow = X + ((size_t)(gm & 63) * T_ + (gm >> 6)) * E_;

    const int bk = tid >> 4;              // 0..15
    const int bj = (tid & 15) * 4;        // 0..60

    unsigned long long accf2[4][4], accb2[4][4];
    const unsigned long long z2 = pk2(0.f, 0.f);
#pragma unroll
    for (int i = 0; i < 4; i++)
#pragma unroll
        for (int j = 0; j < 4; j++) { accf2[i][j] = z2; accb2[i][j] = z2; }

    for (int e0 = 0; e0 < E_; e0 += 16) {
        float4 a0 = *(const float4*)(arow + e0 + lc);
        float4 a1 = *(const float4*)(arow + e0 + lc + 4);
        float4 f4 = *(const float4*)(Wf + (size_t)(e0 + bk) * H_ + j0 + bj);
        float4 b4 = *(const float4*)(Wb + (size_t)(e0 + bk) * H_ + j0 + bj);
        __syncthreads();
        As[lc + 0][lr] = a0.x; As[lc + 1][lr] = a0.y;
        As[lc + 2][lr] = a0.z; As[lc + 3][lr] = a0.w;
        As[lc + 4][lr] = a1.x; As[lc + 5][lr] = a1.y;
        As[lc + 6][lr] = a1.z; As[lc + 7][lr] = a1.w;
        *(float4*)&Bfs[bk][bj] = f4;
        *(float4*)&Bbs[bk][bj] = b4;
        __syncthreads();
#pragma unroll
        for (int kk = 0; kk < 16; kk++) {
            unsigned long long a2[4];
#pragma unroll
            for (int i2 = 0; i2 < 4; i2++) {
                float2 av = *(const float2*)&As[kk][rbase + 2 * i2];
                a2[i2] = pk2(av.x, av.y);
            }
            float4 fv = *(const float4*)&Bfs[kk][cbase];
            float4 bv = *(const float4*)&Bbs[kk][cbase];
            unsigned long long f2[4], b2[4];
            f2[0] = pk2(fv.x, fv.x); f2[1] = pk2(fv.y, fv.y);
            f2[2] = pk2(fv.z, fv.z); f2[3] = pk2(fv.w, fv.w);
            b2[0] = pk2(bv.x, bv.x); b2[1] = pk2(bv.y, bv.y);
            b2[2] = pk2(bv.z, bv.z); b2[3] = pk2(bv.w, bv.w);
#pragma unroll
            for (int i2 = 0; i2 < 4; i2++)
#pragma unroll
                for (int j = 0; j < 4; j++) {
                    FMA2(accf2[i2][j], a2[i2], f2[j], accf2[i2][j]);
                    FMA2(accb2[i2][j], a2[i2], b2[j], accb2[i2][j]);
                }
        }
    }

    // unpack
    float acc_f[8][4], acc_b[8][4];
#pragma unroll
    for (int i2 = 0; i2 < 4; i2++)
#pragma unroll
        for (int j = 0; j < 4; j++) {
            upk2(accf2[i2][j], acc_f[2 * i2][j], acc_f[2 * i2 + 1][j]);
            upk2(accb2[i2][j], acc_b[2 * i2][j], acc_b[2 * i2 + 1][j]);
        }

    // epilogue
#pragma unroll
    for (int i = 0; i < 8; i++) {
        const int m = m0 + rbase + i;
        const int t = m >> 6, b = m & 63;
        const int m2 = (T_ - 1 - t) * B_ + b;      // scan index slot for xb
        float4 vf, vb;
        vf.x = acc_f[i][0] + bfv[j0 + cbase + 0];
        vf.y = acc_f[i][1] + bfv[j0 + cbase + 1];
        vf.z = acc_f[i][2] + bfv[j0 + cbase + 2];
        vf.w = acc_f[i][3] + bfv[j0 + cbase + 3];
        vb.x = acc_b[i][0] + bbv[j0 + cbase + 0];
        vb.y = acc_b[i][1] + bbv[j0 + cbase + 1];
        vb.z = acc_b[i][2] + bbv[j0 + cbase + 2];
        vb.w = acc_b[i][3] + bbv[j0 + cbase + 3];
        *(float4*)&g_xf[(size_t)m  * H_ + j0 + cbase] = vf;
        *(float4*)&g_xb[(size_t)m2 * H_ + j0 + cbase] = vb;
    }
}

// ---------------------------------------------------------------------------
// Kernel 2: persistent per-(batch,direction) recurrent scan, FFMA2.
// 128 blocks, 256 threads. Thread t owns output column j=t.
// W_hh column split: k in [0,160) as 80 f32x2 register pairs,
//                    k in [160,256) as 24 float4 groups in shared.
// ---------------------------------------------------------------------------
extern __shared__ float smem_scan[];

__global__ __launch_bounds__(256) void scan_kernel(
    const float* __restrict__ Whh_f,
    const float* __restrict__ Whh_b,
    float* __restrict__ out)
{
    float*  h_sh = smem_scan;                       // [2][256]
    float4* Wsh4 = (float4*)(smem_scan + 2 * H_);   // [KSH4][256]

    const int t   = threadIdx.x;
    const int dir = blockIdx.x >> 6;    // 0 = fwd, 1 = bwd
    const int b   = blockIdx.x & 63;

    const float* W    = dir ? Whh_b : Whh_f;
    const float* xarr = dir ? g_xb  : g_xf;

    // register W pairs: wreg[p] = {W[2p][t], W[2p+1][t]}
    unsigned long long wreg[KREGP];
#pragma unroll
    for (int p = 0; p < KREGP; p++)
        wreg[p] = pk2(W[(size_t)(2 * p) * H_ + t], W[(size_t)(2 * p + 1) * H_ + t]);
    // shared W float4 groups: Wsh4[r][t] = {W[160+4r..163+4r][t]}
    for (int r = 0; r < KSH4; r++) {
        float4 w;
        w.x = W[(size_t)(160 + 4 * r + 0) * H_ + t];
        w.y = W[(size_t)(160 + 4 * r + 1) * H_ + t];
        w.z = W[(size_t)(160 + 4 * r + 2) * H_ + t];
        w.w = W[(size_t)(160 + 4 * r + 3) * H_ + t];
        Wsh4[r * H_ + t] = w;
    }
    h_sh[t] = 0.f;
    __syncthreads();

    const float* xp = xarr + (size_t)b * H_ + t;  // step stride = B_*H_
    float x_next = xp[0];
    float hlast = 0.f;
    int p = 0;

    const unsigned long long z2 = pk2(0.f, 0.f);

    for (int s = 0; s < T_; ++s) {
        float x_cur = x_next;
        if (s + 1 < T_) x_next = xp[(size_t)(s + 1) * (B_ * H_)];

        const float4* hc4 = (const float4*)(h_sh + p * H_);
        unsigned long long a0 = z2, a1 = z2, a2 = z2, a3 = z2;

        // register-resident W rows: k = 0..159 (40 float4 h loads)
#pragma unroll
        for (int q = 0; q < 40; q++) {
            float4 hv = hc4[q];
            if (q & 1) {
                FMA2(a2, pk2(hv.x, hv.y), wreg[2 * q + 0], a2);
                FMA2(a3, pk2(hv.z, hv.w), wreg[2 * q + 1], a3);
            } else {
                FMA2(a0, pk2(hv.x, hv.y), wreg[2 * q + 0], a0);
                FMA2(a1, pk2(hv.z, hv.w), wreg[2 * q + 1], a1);
            }
        }
        // shared-resident W rows: k = 160..255
#pragma unroll
        for (int r = 0; r < KSH4; r++) {
            float4 hv = hc4[40 + r];
            float4 wv = Wsh4[r * H_ + t];
            FMA2(a0, pk2(hv.x, hv.y), pk2(wv.x, wv.y), a0);
            FMA2(a1, pk2(hv.z, hv.w), pk2(wv.z, wv.w), a1);
        }

        float l0, u0, l1, u1, l2, u2, l3, u3;
        upk2(a0, l0, u0); upk2(a1, l1, u1);
        upk2(a2, l2, u2); upk2(a3, l3, u3);
        float sum = ((l0 + u0) + (l1 + u1)) + ((l2 + u2) + (l3 + u3)) + x_cur;
        float hn = fast_tanh(sum);

        h_sh[(p ^ 1) * H_ + t] = hn;

        const int t_orig = dir ? (T_ - 1 - s) : s;
        g_h[((size_t)(t_orig * B_ + b)) * (2 * H_) + dir * H_ + t] = hn;

        hlast = hn;
        p ^= 1;
        __syncthreads();
    }

    out[(size_t)B_ * T_ * O_ + (size_t)dir * (B_ * H_) + (size_t)b * H_ + t] = hlast;
}

// ---------------------------------------------------------------------------
// Kernel 3: output GEMM  Y[b,t,o] = sum_{k<512} hcat[m][k] * W_hy[k][o] + b_y[o]
// 128x64 tile, BK=16, FFMA2 (rows paired).
// ---------------------------------------------------------------------------
__global__ __launch_bounds__(256) void out_kernel(
    const float* __restrict__ Why, const float* __restrict__ byv,
    float* __restrict__ out)
{
    __shared__ float As[16][132];
    __shared__ float Bs[16][68];

    const int tid = threadIdx.x;
    const int m0 = blockIdx.y * 128;
    const int j0 = blockIdx.x * 64;

    const int rbase = (tid >> 4) * 8;
    const int cbase = (tid & 15) * 4;

    const int lr = tid >> 1;
    const int lc = (tid & 1) * 8;
    const float* arow = g_h + (size_t)(m0 + lr) * (2 * H_);

    const int bk = tid >> 4;
    const int bj = (tid & 15) * 4;

    unsigned long long acc2[4][4];
    const unsigned long long z2 = pk2(0.f, 0.f);
#pragma unroll
    for (int i = 0; i < 4; i++)
#pragma unroll
        for (int j = 0; j < 4; j++) acc2[i][j] = z2;

    for (int e0 = 0; e0 < 2 * H_; e0 += 16) {
        float4 a0 = *(const float4*)(arow + e0 + lc);
        float4 a1 = *(const float4*)(arow + e0 + lc + 4);
        float4 w4 = *(const float4*)(Why + (size_t)(e0 + bk) * O_ + j0 + bj);
        __syncthreads();
        As[lc + 0][lr] = a0.x; As[lc + 1][lr] = a0.y;
        As[lc + 2][lr] = a0.z; As[lc + 3][lr] = a0.w;
        As[lc + 4][lr] = a1.x; As[lc + 5][lr] = a1.y;
        As[lc + 6][lr] = a1.z; As[lc + 7][lr] = a1.w;
        *(float4*)&Bs[bk][bj] = w4;
        __syncthreads();
#pragma unroll
        for (int kk = 0; kk < 16; kk++) {
            unsigned long long a2[4];
#pragma unroll
            for (int i2 = 0; i2 < 4; i2++) {
                float2 av = *(const float2*)&As[kk][rbase + 2 * i2];
                a2[i2] = pk2(av.x, av.y);
            }
            float4 wv = *(const float4*)&Bs[kk][cbase];
            unsigned long long w2[4];
            w2[0] = pk2(wv.x, wv.x); w2[1] = pk2(wv.y, wv.y);
            w2[2] = pk2(wv.z, wv.z); w2[3] = pk2(wv.w, wv.w);
#pragma unroll
            for (int i2 = 0; i2 < 4; i2++)
#pragma unroll
                for (int j = 0; j < 4; j++)
                    FMA2(acc2[i2][j], a2[i2], w2[j], acc2[i2][j]);
        }
    }

    float acc[8][4];
#pragma unroll
    for (int i2 = 0; i2 < 4; i2++)
#pragma unroll
        for (int j = 0; j < 4; j++)
            upk2(acc2[i2][j], acc[2 * i2][j], acc[2 * i2 + 1][j]);

#pragma unroll
    for (int i = 0; i < 8; i++) {
        const int m = m0 + rbase + i;
        const int t = m >> 6, b = m & 63;
        float4 v;
        v.x = acc[i][0] + byv[j0 + cbase + 0];
        v.y = acc[i][1] + byv[j0 + cbase + 1];
        v.z = acc[i][2] + byv[j0 + cbase + 2];
        v.w = acc[i][3] + byv[j0 + cbase + 3];
        *(float4*)&out[((size_t)b * T_ + t) * O_ + j0 + cbase] = v;
    }
}

// ---------------------------------------------------------------------------
// launch
// ---------------------------------------------------------------------------
extern "C" void kernel_launch(void* const* d_in, const int* in_sizes, int n_in,
                              void* d_out, int out_size)
{
    const float* X    = (const float*)d_in[0];
    const float* Wxhf = (const float*)d_in[1];
    const float* Whhf = (const float*)d_in[2];
    const float* bf   = (const float*)d_in[3];
    const float* Wxhb = (const float*)d_in[4];
    const float* Whhb = (const float*)d_in[5];
    const float* bb   = (const float*)d_in[6];
    const float* Why  = (const float*)d_in[7];
    const float* by   = (const float*)d_in[8];
    float* out = (float*)d_out;

    cudaFuncSetAttribute(scan_kernel,
                         cudaFuncAttributeMaxDynamicSharedMemorySize,
                         (int)SMEM_SCAN);

    proj_kernel<<<dim3(4, 256), 256>>>(X, Wxhf, bf, Wxhb, bb);
    scan_kernel<<<128, 256, SMEM_SCAN>>>(Whhf, Whhb, out);
    out_kernel<<<dim3(4, 256), 256>>>(Why, by, out);
}